// round 13
// baseline (speedup 1.0000x reference)
#include <cuda_runtime.h>

// FeatNeighbourCorr R10 (= R9 resubmit after infra failure):
// Gram-map compute inside R5/R8 cp.async pipeline.
// out_k(p) = G_dir(base) * rn(p) * rn(q), q = reflect(p - d_k).
// G_A(r,c)=f(r,c)f(r,c+1)  G_B=f(r,c)f(r+1,c)  G_C=f(r,c)f(r+1,c+1)
// G_D(r,c)=f(r,c+1)f(r+1,c)   (anti-diagonal, box convention)
// Tile 16x32, 160 threads, KC=4 chunks, 2-stage pipeline.

#define HH 256
#define WW 256
#define CC 128
#define HW (HH * WW)
#define TH 16
#define TW 32
#define KC 4
#define NCH (CC / KC)          // 32
#define SR 18                  // staged rows h0-1..h0+16
#define SPC 18                 // staged float2/row: cols w0-2..w0+33
#define SSTR2 20               // float2 stride (16B-aligned rows)
#define PLANE2 (SR * SSTR2)    // 360
#define BUF2 (KC * PLANE2)     // 1440
#define NSLOT (KC * SR * SPC)  // 1296
#define NT 160
#define NCPS 9                 // ceil(1296/160)
#define GSTR 40                // G plane float stride
#define GPLANEF (17 * GSTR)    // 680 floats/plane
#define RNSTR 36

typedef unsigned long long u64;

__device__ __forceinline__ u64 pack2(float lo, float hi) {
    u64 r; asm("mov.b64 %0, {%1,%2};" : "=l"(r) : "f"(lo), "f"(hi)); return r;
}
__device__ __forceinline__ float lo2(u64 a) { return __uint_as_float((unsigned)a); }
__device__ __forceinline__ float hi2(u64 a) { return __uint_as_float((unsigned)(a >> 32)); }
__device__ __forceinline__ void fma2(u64& d, u64 a, u64 b) {
    asm("fma.rn.f32x2 %0, %1, %2, %0;" : "+l"(d) : "l"(a), "l"(b));
}
__device__ __forceinline__ int refl(int x) {
    return x < 0 ? -x : (x > HH - 1 ? 2 * (HH - 1) - x : x);
}

__global__ __launch_bounds__(NT, 4)
void featcorr_r10(const float* __restrict__ feats, float* __restrict__ out) {
    __shared__ alignas(16) u64 pool[2 * BUF2];   // 23040 B
    const int t  = threadIdx.x;
    const int b  = blockIdx.z;
    const int h0 = blockIdx.y * TH;
    const int w0 = blockIdx.x * TW;
    const unsigned sbase = (unsigned)__cvta_generic_to_shared(pool);

    // ---- cp.async slots over (ch, row, pc), chunk-invariant ----
    int src[NCPS]; unsigned dst[NCPS]; bool val[NCPS];
#pragma unroll
    for (int u = 0; u < NCPS; ++u) {
        int s = t + NT * u;
        bool in = s < NSLOT;
        int ss = in ? s : 0;
        int ch = ss / (SR * SPC);
        int r  = ss - ch * (SR * SPC);
        int row = r / SPC, pc = r - row * SPC;
        int gh = refl(h0 - 1 + row);
        int gc = w0 - 2 + 2 * pc;
        bool edge = (gc < 0) || (gc >= WW - 1);
        val[u] = in && !edge;
        src[u] = ch * HW + gh * WW + gc;
        dst[u] = sbase + (unsigned)((ch * PLANE2 + row * SSTR2 + pc) * 8);
    }

    // ---- scalar slots for reflected w-edge pairs ----
    const bool eact = (w0 == 0 || w0 == WW - TW) && (t < KC * SR);  // 72 threads
    int es0 = 0, eidx = 0;
    if (eact) {
        int ch = t / SR, row = t - ch * SR;
        int gh = refl(h0 - 1 + row);
        if (w0 == 0) { es0 = ch * HW + gh * WW + 2;   eidx = ch * PLANE2 + row * SSTR2 + 0; }
        else         { es0 = ch * HW + gh * WW + 254; eidx = ch * PLANE2 + row * SSTR2 + 17; }
    }

    // ---- Gram slot: 153 strips over 17 rows x 9 strips of 4 base cols ----
    const bool gact = t < 153;
    const int gsl = gact ? t : 0;
    const int grr = gsl / 9, gsi = gsl - grr * 9;
    const int gwin = grr * (SSTR2 * 2) + 4 * gsi;   // float idx of 8-float window (row r)
    const bool lastrow = gact && (grr == 16);

    u64 aA1 = 0, aA2 = 0, aB1 = 0, aB2 = 0, aC1 = 0, aC2 = 0, aD1 = 0, aD2 = 0;
    u64 s1 = 0, s2 = 0, sn1 = 0, sn2 = 0;
    float ex = 0.f, ey = 0.f;

    const float* bp = feats + (size_t)b * CC * HW;

    // ---- prologue: chunk 0 ----
    {
#pragma unroll
        for (int u = 0; u < NCPS; ++u)
            if (val[u])
                asm volatile("cp.async.ca.shared.global [%0], [%1], 8;"
                             :: "r"(dst[u]), "l"(bp + src[u]) : "memory");
        asm volatile("cp.async.commit_group;" ::: "memory");
        if (eact) { ex = __ldg(bp + es0); ey = __ldg(bp + es0 - 1); }
    }

    for (int it = 0; it < NCH; ++it) {
        asm volatile("cp.async.wait_group 0;" ::: "memory");
        if (eact)
            reinterpret_cast<float2*>(pool)[(it & 1) * BUF2 + eidx] = make_float2(ex, ey);
        __syncthreads();

        if (it + 1 < NCH) {
            const float* bn = bp + KC * HW;
            unsigned bo = (unsigned)(((it + 1) & 1) * BUF2 * 8);
#pragma unroll
            for (int u = 0; u < NCPS; ++u)
                if (val[u])
                    asm volatile("cp.async.ca.shared.global [%0], [%1], 8;"
                                 :: "r"(dst[u] + bo), "l"(bn + src[u]) : "memory");
            asm volatile("cp.async.commit_group;" ::: "memory");
            if (eact) { ex = __ldg(bn + es0); ey = __ldg(bn + es0 - 1); }
        }

        const float* Bf = reinterpret_cast<const float*>(pool + (it & 1) * BUF2);
#pragma unroll
        for (int ch = 0; ch < KC; ++ch) {
            const float* pr = Bf + ch * (PLANE2 * 2) + gwin;
            float4 Ta = *reinterpret_cast<const float4*>(pr);
            float4 Tb = *reinterpret_cast<const float4*>(pr + 4);
            float4 Na = *reinterpret_cast<const float4*>(pr + 40);
            float4 Nb = *reinterpret_cast<const float4*>(pr + 44);

            u64 m1  = pack2(Ta.y, Ta.z), m2  = pack2(Ta.w, Tb.x);
            u64 mM1 = pack2(Ta.z, Ta.w), mM2 = pack2(Tb.x, Tb.y);
            u64 n1  = pack2(Na.y, Na.z), n2  = pack2(Na.w, Nb.x);
            u64 nM1 = pack2(Na.z, Na.w), nM2 = pack2(Nb.x, Nb.y);

            fma2(aA1, m1, mM1);  fma2(aA2, m2, mM2);
            fma2(aB1, m1, n1);   fma2(aB2, m2, n2);
            fma2(aC1, m1, nM1);  fma2(aC2, m2, nM2);
            fma2(aD1, mM1, n1);  fma2(aD2, mM2, n2);
            fma2(s1, m1, m1);    fma2(s2, m2, m2);
            if (lastrow) { fma2(sn1, n1, n1); fma2(sn2, n2, n2); }
        }
        bp += KC * HW;
    }

    // ---- dump G planes over buffer 0 (safe: buffer1 was last read) ----
    {
        float* GP = reinterpret_cast<float*>(pool);
        if (gact) {
            int cidx = grr * GSTR + 4 * gsi;
            *reinterpret_cast<float4*>(GP + 0 * GPLANEF + cidx) =
                make_float4(lo2(aA1), hi2(aA1), lo2(aA2), hi2(aA2));
            *reinterpret_cast<float4*>(GP + 1 * GPLANEF + cidx) =
                make_float4(lo2(aB1), hi2(aB1), lo2(aB2), hi2(aB2));
            *reinterpret_cast<float4*>(GP + 2 * GPLANEF + cidx) =
                make_float4(lo2(aC1), hi2(aC1), lo2(aC2), hi2(aC2));
            *reinterpret_cast<float4*>(GP + 3 * GPLANEF + cidx) =
                make_float4(lo2(aD1), hi2(aD1), lo2(aD2), hi2(aD2));
        }
    }
    __syncthreads();   // all reads of buffer1 done -> RN may overwrite it
    {
        float* RNP = reinterpret_cast<float*>(pool) + 2 * BUF2;
        if (gact) {
            int ridx = grr * RNSTR + 4 * gsi;
            *reinterpret_cast<float4*>(RNP + ridx) =
                make_float4(rsqrtf(lo2(s1)), rsqrtf(hi2(s1)),
                            rsqrtf(lo2(s2)), rsqrtf(hi2(s2)));
            if (lastrow)
                *reinterpret_cast<float4*>(RNP + 17 * RNSTR + 4 * gsi) =
                    make_float4(rsqrtf(lo2(sn1)), rsqrtf(hi2(sn1)),
                                rsqrtf(lo2(sn2)), rsqrtf(hi2(sn2)));
        }
    }
    __syncthreads();

    // ---- gather epilogue (128 threads; 1x4 output strips) ----
    if (t < 128) {
        const float* GP  = reinterpret_cast<const float*>(pool);
        const float* RNP = reinterpret_cast<const float*>(pool) + 2 * BUF2;
        const int py = t >> 3, px0 = (t & 7) << 2;
        const int h = h0 + py;
        float rp[4];
#pragma unroll
        for (int i = 0; i < 4; ++i)
            rp[i] = RNP[(py + 1) * RNSTR + px0 + 1 + i];

        const int DXa[8] = {1, 1, 0, -1, -1, -1, 0, 1};
        const int DYa[8] = {0, 1, 1, 1, 0, -1, -1, -1};
        float* ob = out + ((size_t)b * 8) * HW + (size_t)h * WW + (w0 + px0);
#pragma unroll
        for (int k = 0; k < 8; ++k) {
            float v[4];
#pragma unroll
            for (int i = 0; i < 4; ++i) {
                int w  = w0 + px0 + i;
                int qh = refl(h - DXa[k]);
                int qw = refl(w - DYa[k]);
                int dir, bh, bw;
                if (DXa[k] == 0)      { dir = 0; bh = h; bw = min(w, qw); }
                else if (DYa[k] == 0) { dir = 1; bh = min(h, qh); bw = w; }
                else {
                    bool dn = qh > h;
                    bh = dn ? h : qh;
                    int ct = dn ? w : qw;   // top pixel col
                    int cb = dn ? qw : w;   // bottom pixel col
                    if (ct < cb) { dir = 2; bw = ct; }
                    else         { dir = 3; bw = cb; }
                }
                float g  = GP[dir * GPLANEF + (bh - h0 + 1) * GSTR + (bw - w0 + 1)];
                float rq = RNP[(qh - h0 + 1) * RNSTR + (qw - w0 + 1)];
                v[i] = g * rp[i] * rq;
            }
            *reinterpret_cast<float4*>(ob + (size_t)k * HW) =
                make_float4(v[0], v[1], v[2], v[3]);
        }
    }
}

extern "C" void kernel_launch(void* const* d_in, const int* in_sizes, int n_in,
                              void* d_out, int out_size) {
    const float* feats = (const float*)d_in[0];
    float* out = (float*)d_out;
    dim3 grid(WW / TW, HH / TH, 8);
    featcorr_r10<<<grid, NT>>>(feats, out);
}

// round 14
// speedup vs baseline: 1.0187x; 1.0187x over previous
#include <cuda_runtime.h>

// FeatNeighbourCorr R11: R8 skeleton + 2x4 output patches (vertical reuse).
// out[b,k,h,w] = <n_p, n_q>, n = f/||f||_C, q = reflect(p - d_k).
// Tile 16x32, NT=64 (thread = 2 rows x 4 cols), KC=2, 2-stage cp.async.

#define HH 256
#define WW 256
#define CC 128
#define HW (HH * WW)
#define TH 16
#define TW 32
#define KC 2
#define NCH (CC / KC)        // 64 iterations
#define SR 18                // staged rows h0-1..h0+16
#define SPC 18               // staged float2/row: cols w0-2..w0+33
#define SSTR2 20             // float2 stride (160B rows, 16B-aligned)
#define SSTRF 40             // float stride
#define PLANE2 (SR * SSTR2)  // 360 f2 per channel plane
#define BUF2 (KC * PLANE2)   // 720 f2 per buffer
#define NSLOTC (SR * SPC)    // 324 pair slots per channel
#define NT 64
#define RNSTR 36

typedef unsigned long long u64;

__device__ __forceinline__ u64 pack2(float lo, float hi) {
    u64 r; asm("mov.b64 %0, {%1,%2};" : "=l"(r) : "f"(lo), "f"(hi)); return r;
}
__device__ __forceinline__ float lo2(u64 a) { return __uint_as_float((unsigned)a); }
__device__ __forceinline__ float hi2(u64 a) { return __uint_as_float((unsigned)(a >> 32)); }
__device__ __forceinline__ void fma2(u64& d, u64 a, u64 b) {
    asm("fma.rn.f32x2 %0, %1, %2, %0;" : "+l"(d) : "l"(a), "l"(b));
}
__device__ __forceinline__ u64 mul2(u64 a, u64 b) {
    u64 r; asm("mul.rn.f32x2 %0, %1, %2;" : "=l"(r) : "l"(a), "l"(b)); return r;
}
__device__ __forceinline__ int refl(int x) {
    return x < 0 ? -x : (x > HH - 1 ? 2 * (HH - 1) - x : x);
}

__global__ __launch_bounds__(NT, 6)
void featcorr_r11(const float* __restrict__ feats, float* __restrict__ out) {
    __shared__ alignas(16) u64 pool[2 * BUF2];   // 11520 B
    const int t  = threadIdx.x;
    const int b  = blockIdx.z;
    const int h0 = blockIdx.y * TH;
    const int w0 = blockIdx.x * TW;
    const unsigned sbase = (unsigned)__cvta_generic_to_shared(pool);

    // ---- cp.async pair slots (per channel; ch offsets added at issue) ----
    int src[6]; unsigned dst[6]; bool val[6];
#pragma unroll
    for (int u = 0; u < 6; ++u) {
        int s = t + NT * u;
        bool in = s < NSLOTC;
        int ss = in ? s : 0;
        int row = ss / SPC, pc = ss - row * SPC;
        int gh = refl(h0 - 1 + row);
        int gc = w0 - 2 + 2 * pc;
        bool edge = (gc < 0) || (gc >= WW - 1);   // pair straddles border
        val[u] = in && !edge;
        src[u] = gh * WW + gc;
        dst[u] = sbase + (unsigned)((row * SSTR2 + pc) * 8);
    }

    // ---- scalar slots for reflected w-edge pairs (36 slots on edge tiles) ----
    const bool eact = (w0 == 0 || w0 == WW - TW) && (t < KC * SR);
    int es0 = 0, eidx = 0;
    if (eact) {
        int ch = t / SR, row = t - ch * SR;
        int gh = refl(h0 - 1 + row);
        if (w0 == 0) { es0 = ch * HW + gh * WW + 2;   eidx = ch * PLANE2 + row * SSTR2 + 0; }
        else         { es0 = ch * HW + gh * WW + 254; eidx = ch * PLANE2 + row * SSTR2 + 17; }
    }

    // ---- halo-ring ssq slots (100 ring pixels, up to 2 per thread) ----
    int roff[2], rnoff[2]; bool ract[2];
#pragma unroll
    for (int u = 0; u < 2; ++u) {
        int s = t + NT * u;
        ract[u] = s < 100;
        int ss = ract[u] ? s : 0;
        int rrow, rcol;
        if (ss < 34)      { rrow = 0;       rcol = 1 + ss; }
        else if (ss < 68) { rrow = SR - 1;  rcol = ss - 33; }
        else if (ss < 84) { rrow = ss - 67; rcol = 1; }
        else              { rrow = ss - 83; rcol = 34; }
        roff[u]  = rrow * SSTRF + rcol;
        rnoff[u] = rrow * RNSTR + rcol;
    }

    // thread -> 2x4 patch: output rows 2g, 2g+1; cols fx..fx+3
    const int g = t >> 3, x = t & 7;
    const int fx = 4 * x;

    u64 accA[8], accB[8], accC[8], accD[8];
#pragma unroll
    for (int k = 0; k < 8; ++k) { accA[k] = accB[k] = accC[k] = accD[k] = 0ull; }
    u64 sq0 = 0, sq1 = 0, sq2 = 0, sq3 = 0;
    float rss0 = 0.f, rss1 = 0.f;
    float ex = 0.f, ey = 0.f;

    const float* bp = feats + (size_t)b * CC * HW;

    // ---- prologue: chunk 0 into buffer 0 ----
    {
#pragma unroll
        for (int u = 0; u < 6; ++u) {
            if (val[u]) {
#pragma unroll
                for (int ch = 0; ch < KC; ++ch)
                    asm volatile("cp.async.ca.shared.global [%0], [%1], 8;"
                                 :: "r"(dst[u] + (unsigned)(ch * PLANE2 * 8)),
                                    "l"(bp + src[u] + ch * HW) : "memory");
            }
        }
        asm volatile("cp.async.commit_group;" ::: "memory");
        if (eact) { ex = __ldg(bp + es0); ey = __ldg(bp + es0 - 1); }
    }

    for (int it = 0; it < NCH; ++it) {
        asm volatile("cp.async.wait_group 0;" ::: "memory");
        if (eact)
            reinterpret_cast<float2*>(pool)[(it & 1) * BUF2 + eidx] = make_float2(ex, ey);
        __syncthreads();

        if (it + 1 < NCH) {
            const float* bn = bp + KC * HW;
            const unsigned bo = (unsigned)(((it + 1) & 1) * BUF2 * 8);
#pragma unroll
            for (int u = 0; u < 6; ++u) {
                if (val[u]) {
#pragma unroll
                    for (int ch = 0; ch < KC; ++ch)
                        asm volatile("cp.async.ca.shared.global [%0], [%1], 8;"
                                     :: "r"(dst[u] + bo + (unsigned)(ch * PLANE2 * 8)),
                                        "l"(bn + src[u] + ch * HW) : "memory");
                }
            }
            asm volatile("cp.async.commit_group;" ::: "memory");
            if (eact) { ex = __ldg(bn + es0); ey = __ldg(bn + es0 - 1); }
        }

        const float* Bf = reinterpret_cast<const float*>(pool + (it & 1) * BUF2);
#pragma unroll
        for (int ch = 0; ch < KC; ++ch) {
            const float* P = Bf + ch * (PLANE2 * 2) + (2 * g) * SSTRF + fx;
            float4 Ar[4], Br[4];
#pragma unroll
            for (int i = 0; i < 4; ++i) {
                Ar[i] = *reinterpret_cast<const float4*>(P + i * SSTRF);
                Br[i] = *reinterpret_cast<const float4*>(P + i * SSTRF + 4);
            }
            u64 M1[4], M2[4], L1[4], L2[4], R2[4];
#pragma unroll
            for (int i = 0; i < 4; ++i) {
                M1[i] = pack2(Ar[i].z, Ar[i].w);
                M2[i] = pack2(Br[i].x, Br[i].y);
                L1[i] = pack2(Ar[i].y, Ar[i].z);
                L2[i] = pack2(Ar[i].w, Br[i].x);
                R2[i] = pack2(Br[i].y, Br[i].z);
            }
            // output row 0 (center loaded row 1)
            fma2(accA[0], M1[1], M1[0]); fma2(accB[0], M2[1], M2[0]);
            fma2(accA[1], M1[1], L1[0]); fma2(accB[1], M2[1], L2[0]);
            fma2(accA[2], M1[1], L1[1]); fma2(accB[2], M2[1], L2[1]);
            fma2(accA[3], M1[1], L1[2]); fma2(accB[3], M2[1], L2[2]);
            fma2(accA[4], M1[1], M1[2]); fma2(accB[4], M2[1], M2[2]);
            fma2(accA[5], M1[1], L2[2]); fma2(accB[5], M2[1], R2[2]);
            fma2(accA[6], M1[1], L2[1]); fma2(accB[6], M2[1], R2[1]);
            fma2(accA[7], M1[1], L2[0]); fma2(accB[7], M2[1], R2[0]);
            // output row 1 (center loaded row 2)
            fma2(accC[0], M1[2], M1[1]); fma2(accD[0], M2[2], M2[1]);
            fma2(accC[1], M1[2], L1[1]); fma2(accD[1], M2[2], L2[1]);
            fma2(accC[2], M1[2], L1[2]); fma2(accD[2], M2[2], L2[2]);
            fma2(accC[3], M1[2], L1[3]); fma2(accD[3], M2[2], L2[3]);
            fma2(accC[4], M1[2], M1[3]); fma2(accD[4], M2[2], M2[3]);
            fma2(accC[5], M1[2], L2[3]); fma2(accD[5], M2[2], R2[3]);
            fma2(accC[6], M1[2], L2[2]); fma2(accD[6], M2[2], R2[2]);
            fma2(accC[7], M1[2], L2[1]); fma2(accD[7], M2[2], R2[1]);
            // sum-of-squares for own pixels
            fma2(sq0, M1[1], M1[1]); fma2(sq1, M2[1], M2[1]);
            fma2(sq2, M1[2], M1[2]); fma2(sq3, M2[2], M2[2]);
            // ring ssq
#pragma unroll
            for (int u = 0; u < 2; ++u) {
                if (ract[u]) {
                    float rv = Bf[ch * (PLANE2 * 2) + roff[u]];
                    if (u) rss1 += rv * rv; else rss0 += rv * rv;
                }
            }
        }
        bp += KC * HW;
    }

    // ---- rsqrt + RN map (aliased over buffer 0; buf0 reads done @ it=62) ----
    float rn00 = rsqrtf(lo2(sq0)), rn01 = rsqrtf(hi2(sq0));
    float rn02 = rsqrtf(lo2(sq1)), rn03 = rsqrtf(hi2(sq1));
    float rn10 = rsqrtf(lo2(sq2)), rn11 = rsqrtf(hi2(sq2));
    float rn12 = rsqrtf(lo2(sq3)), rn13 = rsqrtf(hi2(sq3));
    float* RN = reinterpret_cast<float*>(pool);   // 18 x 36 floats = 2592 B
    *reinterpret_cast<float2*>(RN + (2 * g + 1) * RNSTR + fx + 2) = make_float2(rn00, rn01);
    *reinterpret_cast<float2*>(RN + (2 * g + 1) * RNSTR + fx + 4) = make_float2(rn02, rn03);
    *reinterpret_cast<float2*>(RN + (2 * g + 2) * RNSTR + fx + 2) = make_float2(rn10, rn11);
    *reinterpret_cast<float2*>(RN + (2 * g + 2) * RNSTR + fx + 4) = make_float2(rn12, rn13);
    if (ract[0]) RN[rnoff[0]] = rsqrtf(rss0);
    if (ract[1]) RN[rnoff[1]] = rsqrtf(rss1);
    __syncthreads();

    // ---- epilogue: gather neighbor norms, scale, store ----
    const int DXa[8] = {1, 1, 0, -1, -1, -1, 0, 1};
    const int DYa[8] = {0, 1, 1, 1, 0, -1, -1, -1};
    const int wbase = w0 + fx;
    float* ob = out + ((size_t)b * 8) * HW;
    const u64 rpA0 = pack2(rn00, rn01), rpB0 = pack2(rn02, rn03);
    const u64 rpA1 = pack2(rn10, rn11), rpB1 = pack2(rn12, rn13);
#pragma unroll
    for (int j = 0; j < 2; ++j) {
        const int h = h0 + 2 * g + j;
        const u64 rpA = j ? rpA1 : rpA0;
        const u64 rpB = j ? rpB1 : rpB0;
#pragma unroll
        for (int k = 0; k < 8; ++k) {
            int qrow = refl(h - DXa[k]) - h0 + 1;
            float rq[4];
#pragma unroll
            for (int i = 0; i < 4; ++i) {
                int qw = refl(wbase + i - DYa[k]);
                rq[i] = RN[qrow * RNSTR + (qw - w0 + 2)];
            }
            u64 aP = j ? accC[k] : accA[k];
            u64 aQ = j ? accD[k] : accB[k];
            u64 o1 = mul2(mul2(aP, rpA), pack2(rq[0], rq[1]));
            u64 o2 = mul2(mul2(aQ, rpB), pack2(rq[2], rq[3]));
            *reinterpret_cast<float4*>(ob + (size_t)k * HW + (size_t)h * WW + wbase) =
                make_float4(lo2(o1), hi2(o1), lo2(o2), hi2(o2));
        }
    }
}

extern "C" void kernel_launch(void* const* d_in, const int* in_sizes, int n_in,
                              void* d_out, int out_size) {
    const float* feats = (const float*)d_in[0];
    float* out = (float*)d_out;
    dim3 grid(WW / TW, HH / TH, 8);
    featcorr_r11<<<grid, NT>>>(feats, out);
}